// round 11
// baseline (speedup 1.0000x reference)
#include <cuda_runtime.h>
#include <cuda_bf16.h>
#include <math.h>
#include <stdint.h>
#include <stddef.h>

// ---------------- problem constants ----------------
#define T_STEPS 2048
#define BATCH   64
#define D_IN    512
#define D_HID   512
#define MROWS   (T_STEPS * BATCH)        // 131072
#define XCOLS   1536                     // r | z | g pre-activations from x

// ---------------- recurrent kernel topology ----------------
#define NGROUPS 8
#define CPG     16                       // CTAs per group
#define NCTAS   (NGROUPS * CPG)          // 128 (single wave on 148+ SMs)
#define BLOC    (BATCH / NGROUPS)        // 8 batches per group
#define RPC     (D_HID / CPG)            // 32 hidden rows per CTA per gate
#define RTHREADS 512

// ---------------- device scratch (static; no allocation APIs) ----------------
__device__ float g_Xbuf[(size_t)MROWS * XCOLS];   // [t*64+b][1536]
__device__ float g_h[BATCH * D_HID];              // hidden state
__device__ float g_rh[BATCH * D_HID];             // r * h
__device__ unsigned g_cnt1[NGROUPS];              // barrier 1 arrivals (8/CTA)
__device__ unsigned g_gen1[NGROUPS];
__device__ unsigned g_cnt2[NGROUPS];              // barrier 2 arrivals (1/CTA)
__device__ unsigned g_gen2[NGROUPS];

// ---------------- packed fp32x2 FMA ----------------
union F2 { float2 f; unsigned long long u; };
__device__ __forceinline__ void ffma2(F2& c, float2 a, float2 b) {
    F2 A, B; A.f = a; B.f = b;
    asm("fma.rn.f32x2 %0, %1, %2, %0;" : "+l"(c.u) : "l"(A.u), "l"(B.u));
}

// ---------------- acquire/release sync primitives (no CCTL fences) -------
__device__ __forceinline__ unsigned ld_acq(const unsigned* p) {
    unsigned v;
    asm volatile("ld.acquire.gpu.u32 %0, [%1];" : "=r"(v) : "l"(p) : "memory");
    return v;
}
__device__ __forceinline__ unsigned atom_add_rel(unsigned* p, unsigned v) {
    unsigned old;
    asm volatile("atom.add.release.gpu.u32 %0, [%1], %2;"
                 : "=r"(old) : "l"(p), "r"(v) : "memory");
    return old;
}
__device__ __forceinline__ void st_rel_u32(unsigned* p, unsigned v) {
    asm volatile("st.release.gpu.u32 [%0], %1;" :: "l"(p), "r"(v) : "memory");
}
__device__ __forceinline__ void st_rlx_u32(unsigned* p, unsigned v) {
    asm volatile("st.relaxed.gpu.u32 [%0], %1;" :: "l"(p), "r"(v) : "memory");
}
__device__ __forceinline__ void stg_strong(float* p, float v) {
    asm volatile("st.relaxed.gpu.f32 [%0], %1;" :: "l"(p), "f"(v) : "memory");
}

// =====================================================================
// Kernel A: input projection GEMM (unchanged from R10)
// =====================================================================
__global__ void __launch_bounds__(256, 2) xproj_kernel(
    const float* __restrict__ x,
    const float* __restrict__ Wr, const float* __restrict__ br,
    const float* __restrict__ Wz, const float* __restrict__ bz,
    const float* __restrict__ Wg, const float* __restrict__ bg)
{
    __shared__ float As[2][16][132];
    __shared__ float Bs[2][16][132];

    const int bm = blockIdx.x;
    const int bn = blockIdx.y;
    const int gate = bn >> 2;
    const int nb   = (bn & 3) << 7;
    const float* W    = (gate == 0) ? Wr : (gate == 1) ? Wz : Wg;
    const float* bias = (gate == 0) ? br : (gate == 1) ? bz : bg;
    const int m0 = bm << 7;

    const int tid = threadIdx.x;
    const int tx = tid & 15, ty = tid >> 4;
    const int lr  = tid >> 2;
    const int lc4 = (tid & 3) << 2;

    const float* xa = x + (size_t)(m0 + lr)      * 512  + lc4;
    const float* xb = x + (size_t)(m0 + lr + 64) * 512  + lc4;
    const float* wa = W + (size_t)(nb + lr)      * 1024 + lc4;
    const float* wb = W + (size_t)(nb + lr + 64) * 1024 + lc4;

    F2 acc2[4][8];
#pragma unroll
    for (int i = 0; i < 4; i++)
#pragma unroll
        for (int j = 0; j < 8; j++) acc2[i][j].u = 0ull;

    {
        float4 a0 = *(const float4*)xa;
        float4 a1 = *(const float4*)xb;
        float4 w0 = *(const float4*)wa;
        float4 w1 = *(const float4*)wb;
        const float av0[4] = {a0.x, a0.y, a0.z, a0.w};
        const float av1[4] = {a1.x, a1.y, a1.z, a1.w};
        const float wv0[4] = {w0.x, w0.y, w0.z, w0.w};
        const float wv1[4] = {w1.x, w1.y, w1.z, w1.w};
#pragma unroll
        for (int u = 0; u < 4; u++) {
            As[0][lc4 + u][lr]      = av0[u];
            As[0][lc4 + u][lr + 64] = av1[u];
            Bs[0][lc4 + u][lr]      = wv0[u];
            Bs[0][lc4 + u][lr + 64] = wv1[u];
        }
    }
    __syncthreads();

    int buf = 0;
#pragma unroll 1
    for (int t = 0; t < 32; t++) {
        float4 a0n, a1n, w0n, w1n;
        if (t < 31) {
            int k0 = (t + 1) << 4;
            a0n = *(const float4*)(xa + k0);
            a1n = *(const float4*)(xb + k0);
            w0n = *(const float4*)(wa + k0);
            w1n = *(const float4*)(wb + k0);
        }
#pragma unroll
        for (int kk = 0; kk < 16; kk++) {
            float4 av0 = *(const float4*)&As[buf][kk][ty * 4];
            float4 av1 = *(const float4*)&As[buf][kk][64 + ty * 4];
            float4 bv0 = *(const float4*)&Bs[buf][kk][tx * 4];
            float4 bv1 = *(const float4*)&Bs[buf][kk][64 + tx * 4];
            float2 ap[4] = { {av0.x, av0.y}, {av0.z, av0.w},
                             {av1.x, av1.y}, {av1.z, av1.w} };
            float  b_[8] = {bv0.x, bv0.y, bv0.z, bv0.w,
                            bv1.x, bv1.y, bv1.z, bv1.w};
#pragma unroll
            for (int jj = 0; jj < 8; jj++) {
                float2 bd = {b_[jj], b_[jj]};
#pragma unroll
                for (int i2 = 0; i2 < 4; i2++)
                    ffma2(acc2[i2][jj], ap[i2], bd);
            }
        }
        if (t < 31) {
            int nx = buf ^ 1;
            const float av0[4] = {a0n.x, a0n.y, a0n.z, a0n.w};
            const float av1[4] = {a1n.x, a1n.y, a1n.z, a1n.w};
            const float wv0[4] = {w0n.x, w0n.y, w0n.z, w0n.w};
            const float wv1[4] = {w1n.x, w1n.y, w1n.z, w1n.w};
#pragma unroll
            for (int u = 0; u < 4; u++) {
                As[nx][lc4 + u][lr]      = av0[u];
                As[nx][lc4 + u][lr + 64] = av1[u];
                Bs[nx][lc4 + u][lr]      = wv0[u];
                Bs[nx][lc4 + u][lr + 64] = wv1[u];
            }
        }
        __syncthreads();
        buf ^= 1;
    }

    const int colbase = gate * 512 + nb;
#pragma unroll
    for (int i = 0; i < 8; i++) {
        int m = m0 + ((i < 4) ? (ty * 4 + i) : (64 + ty * 4 + (i - 4)));
        const F2* ar = acc2[i >> 1];
        float av[8];
#pragma unroll
        for (int j = 0; j < 8; j++)
            av[j] = (i & 1) ? ar[j].f.y : ar[j].f.x;
        float4 v0, v1;
        v0.x = av[0] + __ldg(&bias[nb + tx * 4 + 0]);
        v0.y = av[1] + __ldg(&bias[nb + tx * 4 + 1]);
        v0.z = av[2] + __ldg(&bias[nb + tx * 4 + 2]);
        v0.w = av[3] + __ldg(&bias[nb + tx * 4 + 3]);
        v1.x = av[4] + __ldg(&bias[nb + 64 + tx * 4 + 0]);
        v1.y = av[5] + __ldg(&bias[nb + 64 + tx * 4 + 1]);
        v1.z = av[6] + __ldg(&bias[nb + 64 + tx * 4 + 2]);
        v1.w = av[7] + __ldg(&bias[nb + 64 + tx * 4 + 3]);
        *(float4*)&g_Xbuf[(size_t)m * XCOLS + colbase + tx * 4]      = v0;
        *(float4*)&g_Xbuf[(size_t)m * XCOLS + colbase + 64 + tx * 4] = v1;
    }
}

__device__ __forceinline__ float fast_sigmoid(float v) {
    return 1.0f / (1.0f + __expf(-v));
}
__device__ __forceinline__ float fast_tanh(float v) {
    return 1.0f - 2.0f / (__expf(2.0f * v) + 1.0f);
}

// warp tree reduction: 32 accs over 32 lanes; lane l ends with sum of acc l.
__device__ __forceinline__ void reduce32(float* acc, int lane) {
#pragma unroll
    for (int off = 16; off >= 1; off >>= 1) {
        const int half = off;
        const bool up = (lane & off) != 0;
#pragma unroll
        for (int i = 0; i < 16; i++) {
            if (i < half) {
                float send = up ? acc[i] : acc[i + half];
                float got  = __shfl_xor_sync(0xffffffffu, send, off);
                acc[i] = (up ? acc[i + half] : acc[i]) + got;
            }
        }
    }
}
// 16 accs over 32 lanes; lane pair {2o,2o+1} both end with sum of acc o=lane>>1.
__device__ __forceinline__ void reduce16dup(float* acc, int lane) {
#pragma unroll
    for (int off = 16; off >= 2; off >>= 1) {
        const int half = off >> 1;
        const bool up = (lane & off) != 0;
#pragma unroll
        for (int i = 0; i < 8; i++) {
            if (i < half) {
                float send = up ? acc[i] : acc[i + half];
                float got  = __shfl_xor_sync(0xffffffffu, send, off);
                acc[i] = (up ? acc[i + half] : acc[i]) + got;
            }
        }
    }
    acc[0] += __shfl_xor_sync(0xffffffffu, acc[0], 1);
}

// =====================================================================
// Kernel B: persistent recurrence, r-first scheduling + acq/rel barriers.
// 128 CTAs x 512 threads, 1 CTA/SM. Group g (16 CTAs) owns batches
// [8g,8g+8); CTA owns hidden rows [32*cid, 32*cid+32).
// =====================================================================
__global__ void __launch_bounds__(RTHREADS, 1) gru_rec_kernel(
    float* __restrict__ out,
    const float* __restrict__ Wr,
    const float* __restrict__ Wz,
    const float* __restrict__ Wg,
    int write_final)
{
    extern __shared__ float sm[];
    float* wrz = sm;                    // [64][512] rows 0..31 Wr_h, 32..63 Wz_h
    float* wg  = wrz + 64 * 512;        // [32][512] Wg_h
    float* hs  = wg  + 32 * 512;        // [8][512]  h (phase1) / r*h (phase2)
    float* zs  = hs  + 8 * 512;         // [8][32]
    float* hps = zs  + 256;             // [8][32]
    float* pr  = hps + 256;             // [8][32]   cross-k-half partials

    const int cta = blockIdx.x;
    const int grp = cta >> 4;
    const int cid = cta & 15;
    const int n0 = cid * RPC;
    const int b0 = grp * BLOC;
    const int tid = threadIdx.x;
    const int w = tid >> 5, lane = tid & 31;

    // ---- load hidden-part weights into smem (once) ----
    for (int idx = tid; idx < 64 * 128; idx += RTHREADS) {
        int row = idx >> 7, c4 = idx & 127;
        const float* W = (row < 32) ? Wr : Wz;
        int n = n0 + (row & 31);
        ((float4*)wrz)[idx] = *(const float4*)&W[(size_t)n * 1024 + 512 + c4 * 4];
    }
    for (int idx = tid; idx < 32 * 128; idx += RTHREADS) {
        int row = idx >> 7, c4 = idx & 127;
        ((float4*)wg)[idx] = *(const float4*)&Wg[(size_t)(n0 + row) * 1024 + 512 + c4 * 4];
    }
    __syncthreads();

    // phase1 mapping: 8 warp slots x 2 k-halves; slot tile = 4 batches x 8 rows
    const int khalf = w >> 3;                       // 0 or 1
    const int slot  = w & 7;
    const int bb = (slot & 1) * 4;
    const int rb = (slot >> 1) * 8;                 // 0,8,16,24
    const int p1_bl  = bb + (lane >> 3);            // finalize coords
    const int p1_row = rb + (lane & 7);             // 0..31
    const int p1_n   = n0 + p1_row;
    const int p1_b   = b0 + p1_bl;
    const int p1_col = (khalf == 0) ? p1_n : (512 + p1_n);  // w<8: r, w>=8: z
    // phase2 mapping: warp tile 4 batches x 4 rows; output o2 = lane>>1
    const int p2_bb = (w & 1) * 4;
    const int p2_rb = (w >> 1) * 4;
    const int o2    = lane >> 1;
    const int p2_bl = p2_bb + (o2 >> 2);
    const int p2_nl = p2_rb + (o2 & 3);
    const int p2_b  = b0 + p2_bl;
    const int p2_n  = n0 + p2_nl;

    const float4* hs4  = (const float4*)hs;
    const float4* wrz4 = (const float4*)wrz;
    const float4* wg4  = (const float4*)wg;

    const float* xrow = g_Xbuf;
    for (int t = 0; t < T_STEPS; t++, xrow += (size_t)BATCH * XCOLS) {
        // generation snapshots (before any of our arrivals this step)
        const unsigned my1 = ld_acq(&g_gen1[grp]);
        const unsigned my2 = ld_acq(&g_gen2[grp]);

        // prefetch x pre-activations for this step
        float x1v = __ldg(&xrow[(size_t)p1_b * XCOLS + p1_col]);
        float x2v = __ldg(&xrow[(size_t)p2_b * XCOLS + 1024 + p2_n]);

        // ---- stage h (zeros at t==0; strong-stored by peers, read via L2) ----
        if (t == 0) {
            float4 z4 = {0.f, 0.f, 0.f, 0.f};
#pragma unroll
            for (int it = 0; it < 2; it++)
                ((float4*)hs)[tid + it * RTHREADS] = z4;
        } else {
#pragma unroll
            for (int it = 0; it < 2; it++) {
                int idx = tid + it * RTHREADS;
                ((float4*)hs)[idx] = __ldcg(&((const float4*)g_h)[b0 * 128 + idx]);
            }
        }
        __syncthreads();

        // ================= phase 1a: r (all warps, k-split 2) =================
        {
            F2 acc[32];
#pragma unroll
            for (int i = 0; i < 32; i++) acc[i].u = 0ull;
#pragma unroll
            for (int j = 0; j < 2; j++) {
                const int o = khalf * 64 + j * 32 + lane;
                float4 hv[4];
#pragma unroll
                for (int bbx = 0; bbx < 4; bbx++)
                    hv[bbx] = hs4[(bb + bbx) * 128 + o];
#pragma unroll
                for (int rr = 0; rr < 8; rr++) {
                    float4 wv = wrz4[(rb + rr) * 128 + o];
                    float2 wlo = {wv.x, wv.y}, whi = {wv.z, wv.w};
#pragma unroll
                    for (int bbx = 0; bbx < 4; bbx++) {
                        ffma2(acc[bbx * 8 + rr], make_float2(hv[bbx].x, hv[bbx].y), wlo);
                        ffma2(acc[bbx * 8 + rr], make_float2(hv[bbx].z, hv[bbx].w), whi);
                    }
                }
            }
            float accs[32];
#pragma unroll
            for (int i = 0; i < 32; i++) accs[i] = acc[i].f.x + acc[i].f.y;
            reduce32(accs, lane);
            if (khalf == 1) pr[slot * 32 + lane] = accs[0];
            __syncthreads();
            if (khalf == 0) {
                float tot = accs[0] + pr[slot * 32 + lane];
                float rv = fast_sigmoid(x1v + tot);
                stg_strong(&g_rh[p1_b * 512 + p1_n], rv * hs[p1_bl * 512 + p1_n]);
                __syncwarp();
                if (lane == 0) {                      // early per-warp release
                    unsigned old = atom_add_rel(&g_cnt1[grp], 1u);
                    if (old == 8u * CPG - 1u) {
                        st_rlx_u32(&g_cnt1[grp], 0u);
                        st_rel_u32(&g_gen1[grp], my1 + 1u);
                    }
                }
            }
        }

        // ================= phase 1b: z (all warps, k-split 2) =================
        {
            F2 acc[32];
#pragma unroll
            for (int i = 0; i < 32; i++) acc[i].u = 0ull;
#pragma unroll
            for (int j = 0; j < 2; j++) {
                const int o = khalf * 64 + j * 32 + lane;
                float4 hv[4];
#pragma unroll
                for (int bbx = 0; bbx < 4; bbx++)
                    hv[bbx] = hs4[(bb + bbx) * 128 + o];
#pragma unroll
                for (int rr = 0; rr < 8; rr++) {
                    float4 wv = wrz4[(32 + rb + rr) * 128 + o];
                    float2 wlo = {wv.x, wv.y}, whi = {wv.z, wv.w};
#pragma unroll
                    for (int bbx = 0; bbx < 4; bbx++) {
                        ffma2(acc[bbx * 8 + rr], make_float2(hv[bbx].x, hv[bbx].y), wlo);
                        ffma2(acc[bbx * 8 + rr], make_float2(hv[bbx].z, hv[bbx].w), whi);
                    }
                }
            }
            float accs[32];
#pragma unroll
            for (int i = 0; i < 32; i++) accs[i] = acc[i].f.x + acc[i].f.y;
            reduce32(accs, lane);
            if (khalf == 0) pr[slot * 32 + lane] = accs[0];
            __syncthreads();
            if (khalf == 1) {
                float tot = accs[0] + pr[slot * 32 + lane];
                zs[p1_bl * 32 + p1_row]  = fast_sigmoid(x1v + tot);
                hps[p1_bl * 32 + p1_row] = hs[p1_bl * 512 + p1_n];
            }
        }
        __syncthreads();                 // z-finalize done; hs free to overwrite

        // wait for all groups' r*h (mostly already flipped — hidden by z work)
        while (ld_acq(&g_gen1[grp]) == my1) { }

        // ---- stage r*h (overwrites hs) ----
#pragma unroll
        for (int it = 0; it < 2; it++) {
            int idx = tid + it * RTHREADS;
            ((float4*)hs)[idx] = __ldcg(&((const float4*)g_rh)[b0 * 128 + idx]);
        }
        __syncthreads();

        // ================= phase 2: g and h update =================
        {
            F2 acc[16];
#pragma unroll
            for (int i = 0; i < 16; i++) acc[i].u = 0ull;
#pragma unroll
            for (int j = 0; j < 4; j++) {
                const int o = lane + j * 32;
                float4 hv[4];
#pragma unroll
                for (int bbx = 0; bbx < 4; bbx++)
                    hv[bbx] = hs4[(p2_bb + bbx) * 128 + o];
#pragma unroll
                for (int rr = 0; rr < 4; rr++) {
                    float4 wv = wg4[(p2_rb + rr) * 128 + o];
                    float2 wlo = {wv.x, wv.y}, whi = {wv.z, wv.w};
#pragma unroll
                    for (int bbx = 0; bbx < 4; bbx++) {
                        ffma2(acc[bbx * 4 + rr], make_float2(hv[bbx].x, hv[bbx].y), wlo);
                        ffma2(acc[bbx * 4 + rr], make_float2(hv[bbx].z, hv[bbx].w), whi);
                    }
                }
            }
            float accs[16];
#pragma unroll
            for (int i = 0; i < 16; i++) accs[i] = acc[i].f.x + acc[i].f.y;
            reduce16dup(accs, lane);
            if ((lane & 1) == 0) {
                float gv = fast_tanh(x2v + accs[0]);
                float zv = zs[p2_bl * 32 + p2_nl];
                float hp = hps[p2_bl * 32 + p2_nl];
                float hn = zv * hp + (1.0f - zv) * gv;
                stg_strong(&g_h[p2_b * 512 + p2_n], hn);
                out[((size_t)t * BATCH + p2_b) * 512 + p2_n] = hn;
                if (write_final && t == T_STEPS - 1)
                    out[(size_t)T_STEPS * BATCH * 512 + p2_b * 512 + p2_n] = hn;
            }
        }
        __syncthreads();
        if (tid == 0) {
            unsigned old = atom_add_rel(&g_cnt2[grp], 1u);
            if (old == CPG - 1u) {
                st_rlx_u32(&g_cnt2[grp], 0u);
                st_rel_u32(&g_gen2[grp], my2 + 1u);
            }
        }
        if (t < T_STEPS - 1) {
            while (ld_acq(&g_gen2[grp]) == my2) { }
        }
    }
}

// =====================================================================
extern "C" void kernel_launch(void* const* d_in, const int* in_sizes, int n_in,
                              void* d_out, int out_size) {
    const float* x  = (const float*)d_in[0];
    const float* Wr = (const float*)d_in[1];
    const float* br = (const float*)d_in[2];
    const float* Wz = (const float*)d_in[3];
    const float* bz = (const float*)d_in[4];
    const float* Wg = (const float*)d_in[5];
    const float* bg = (const float*)d_in[6];
    float* out = (float*)d_out;

    dim3 gdim(MROWS / 128, XCOLS / 128);
    xproj_kernel<<<gdim, 256>>>(x, Wr, br, Wz, bz, Wg, bg);

    long long need = (long long)T_STEPS * BATCH * D_HID + (long long)BATCH * D_HID;
    int write_final = ((long long)out_size >= need) ? 1 : 0;

    // smem: wrz 131072 + wg 65536 + hs 16384 + zs 1024 + hps 1024 + pr 1024
    const int smem_bytes = (64 * 512 + 32 * 512 + 8 * 512 + 256 + 256 + 256) * 4;
    cudaFuncSetAttribute(gru_rec_kernel,
                         cudaFuncAttributeMaxDynamicSharedMemorySize, smem_bytes);
    gru_rec_kernel<<<NCTAS, RTHREADS, smem_bytes>>>(out, Wr, Wz, Wg, write_final);
}

// round 12
// speedup vs baseline: 1.1253x; 1.1253x over previous
#include <cuda_runtime.h>
#include <cuda_bf16.h>
#include <math.h>
#include <stdint.h>
#include <stddef.h>

// ---------------- problem constants ----------------
#define T_STEPS 2048
#define BATCH   64
#define D_IN    512
#define D_HID   512
#define MROWS   (T_STEPS * BATCH)        // 131072
#define XCOLS   1536                     // r | z | g pre-activations from x

// ---------------- recurrent kernel topology ----------------
#define NGROUPS 8
#define CPG     16                       // CTAs per group
#define NCTAS   (NGROUPS * CPG)          // 128 (single wave)
#define BLOC    (BATCH / NGROUPS)        // 8 batches per group
#define RPC     (D_HID / CPG)            // 32 hidden rows per CTA per gate
#define RTHREADS 512

// ---------------- device scratch (static; no allocation APIs) ----------------
__device__ float g_Xbuf[(size_t)MROWS * XCOLS];   // [t*64+b][1536]
__device__ float g_h[BATCH * D_HID];              // hidden state
__device__ float g_rh[BATCH * D_HID];             // r * h
__device__ unsigned g_cnt1[NGROUPS];
__device__ unsigned g_gen1[NGROUPS];
__device__ unsigned g_cnt2[NGROUPS];
__device__ unsigned g_gen2[NGROUPS];

// ---------------- packed fp32x2 FMA (xproj only) ----------------
union F2 { float2 f; unsigned long long u; };
__device__ __forceinline__ void ffma2(F2& c, float2 a, float2 b) {
    F2 A, B; A.f = a; B.f = b;
    asm("fma.rn.f32x2 %0, %1, %2, %0;" : "+l"(c.u) : "l"(A.u), "l"(B.u));
}

// ---------------- acquire/release sync primitives (no CCTL fences) -------
__device__ __forceinline__ unsigned ld_acq(const unsigned* p) {
    unsigned v;
    asm volatile("ld.acquire.gpu.u32 %0, [%1];" : "=r"(v) : "l"(p) : "memory");
    return v;
}
__device__ __forceinline__ unsigned atom_add_rel(unsigned* p, unsigned v) {
    unsigned old;
    asm volatile("atom.add.release.gpu.u32 %0, [%1], %2;"
                 : "=r"(old) : "l"(p), "r"(v) : "memory");
    return old;
}
__device__ __forceinline__ void st_rel_u32(unsigned* p, unsigned v) {
    asm volatile("st.release.gpu.u32 [%0], %1;" :: "l"(p), "r"(v) : "memory");
}
__device__ __forceinline__ void st_rlx_u32(unsigned* p, unsigned v) {
    asm volatile("st.relaxed.gpu.u32 [%0], %1;" :: "l"(p), "r"(v) : "memory");
}
__device__ __forceinline__ void stg_strong(float* p, float v) {
    asm volatile("st.relaxed.gpu.f32 [%0], %1;" :: "l"(p), "f"(v) : "memory");
}

// =====================================================================
// Kernel A: input projection GEMM (FFMA2 m-packed, R7-validated)
// =====================================================================
__global__ void __launch_bounds__(256, 2) xproj_kernel(
    const float* __restrict__ x,
    const float* __restrict__ Wr, const float* __restrict__ br,
    const float* __restrict__ Wz, const float* __restrict__ bz,
    const float* __restrict__ Wg, const float* __restrict__ bg)
{
    __shared__ float As[2][16][132];
    __shared__ float Bs[2][16][132];

    const int bm = blockIdx.x;
    const int bn = blockIdx.y;
    const int gate = bn >> 2;
    const int nb   = (bn & 3) << 7;
    const float* W    = (gate == 0) ? Wr : (gate == 1) ? Wz : Wg;
    const float* bias = (gate == 0) ? br : (gate == 1) ? bz : bg;
    const int m0 = bm << 7;

    const int tid = threadIdx.x;
    const int tx = tid & 15, ty = tid >> 4;
    const int lr  = tid >> 2;
    const int lc4 = (tid & 3) << 2;

    const float* xa = x + (size_t)(m0 + lr)      * 512  + lc4;
    const float* xb = x + (size_t)(m0 + lr + 64) * 512  + lc4;
    const float* wa = W + (size_t)(nb + lr)      * 1024 + lc4;
    const float* wb = W + (size_t)(nb + lr + 64) * 1024 + lc4;

    F2 acc2[4][8];
#pragma unroll
    for (int i = 0; i < 4; i++)
#pragma unroll
        for (int j = 0; j < 8; j++) acc2[i][j].u = 0ull;

    {
        float4 a0 = *(const float4*)xa;
        float4 a1 = *(const float4*)xb;
        float4 w0 = *(const float4*)wa;
        float4 w1 = *(const float4*)wb;
        const float av0[4] = {a0.x, a0.y, a0.z, a0.w};
        const float av1[4] = {a1.x, a1.y, a1.z, a1.w};
        const float wv0[4] = {w0.x, w0.y, w0.z, w0.w};
        const float wv1[4] = {w1.x, w1.y, w1.z, w1.w};
#pragma unroll
        for (int u = 0; u < 4; u++) {
            As[0][lc4 + u][lr]      = av0[u];
            As[0][lc4 + u][lr + 64] = av1[u];
            Bs[0][lc4 + u][lr]      = wv0[u];
            Bs[0][lc4 + u][lr + 64] = wv1[u];
        }
    }
    __syncthreads();

    int buf = 0;
#pragma unroll 1
    for (int t = 0; t < 32; t++) {
        float4 a0n, a1n, w0n, w1n;
        if (t < 31) {
            int k0 = (t + 1) << 4;
            a0n = *(const float4*)(xa + k0);
            a1n = *(const float4*)(xb + k0);
            w0n = *(const float4*)(wa + k0);
            w1n = *(const float4*)(wb + k0);
        }
#pragma unroll
        for (int kk = 0; kk < 16; kk++) {
            float4 av0 = *(const float4*)&As[buf][kk][ty * 4];
            float4 av1 = *(const float4*)&As[buf][kk][64 + ty * 4];
            float4 bv0 = *(const float4*)&Bs[buf][kk][tx * 4];
            float4 bv1 = *(const float4*)&Bs[buf][kk][64 + tx * 4];
            float2 ap[4] = { {av0.x, av0.y}, {av0.z, av0.w},
                             {av1.x, av1.y}, {av1.z, av1.w} };
            float  b_[8] = {bv0.x, bv0.y, bv0.z, bv0.w,
                            bv1.x, bv1.y, bv1.z, bv1.w};
#pragma unroll
            for (int jj = 0; jj < 8; jj++) {
                float2 bd = {b_[jj], b_[jj]};
#pragma unroll
                for (int i2 = 0; i2 < 4; i2++)
                    ffma2(acc2[i2][jj], ap[i2], bd);
            }
        }
        if (t < 31) {
            int nx = buf ^ 1;
            const float av0[4] = {a0n.x, a0n.y, a0n.z, a0n.w};
            const float av1[4] = {a1n.x, a1n.y, a1n.z, a1n.w};
            const float wv0[4] = {w0n.x, w0n.y, w0n.z, w0n.w};
            const float wv1[4] = {w1n.x, w1n.y, w1n.z, w1n.w};
#pragma unroll
            for (int u = 0; u < 4; u++) {
                As[nx][lc4 + u][lr]      = av0[u];
                As[nx][lc4 + u][lr + 64] = av1[u];
                Bs[nx][lc4 + u][lr]      = wv0[u];
                Bs[nx][lc4 + u][lr + 64] = wv1[u];
            }
        }
        __syncthreads();
        buf ^= 1;
    }

    const int colbase = gate * 512 + nb;
#pragma unroll
    for (int i = 0; i < 8; i++) {
        int m = m0 + ((i < 4) ? (ty * 4 + i) : (64 + ty * 4 + (i - 4)));
        const F2* ar = acc2[i >> 1];
        float av[8];
#pragma unroll
        for (int j = 0; j < 8; j++)
            av[j] = (i & 1) ? ar[j].f.y : ar[j].f.x;
        float4 v0, v1;
        v0.x = av[0] + __ldg(&bias[nb + tx * 4 + 0]);
        v0.y = av[1] + __ldg(&bias[nb + tx * 4 + 1]);
        v0.z = av[2] + __ldg(&bias[nb + tx * 4 + 2]);
        v0.w = av[3] + __ldg(&bias[nb + tx * 4 + 3]);
        v1.x = av[4] + __ldg(&bias[nb + 64 + tx * 4 + 0]);
        v1.y = av[5] + __ldg(&bias[nb + 64 + tx * 4 + 1]);
        v1.z = av[6] + __ldg(&bias[nb + 64 + tx * 4 + 2]);
        v1.w = av[7] + __ldg(&bias[nb + 64 + tx * 4 + 3]);
        *(float4*)&g_Xbuf[(size_t)m * XCOLS + colbase + tx * 4]      = v0;
        *(float4*)&g_Xbuf[(size_t)m * XCOLS + colbase + 64 + tx * 4] = v1;
    }
}

__device__ __forceinline__ float dot4f(float4 a, float4 b) {
    return a.x * b.x + a.y * b.y + a.z * b.z + a.w * b.w;
}
__device__ __forceinline__ float fast_sigmoid(float v) {
    return 1.0f / (1.0f + __expf(-v));
}
__device__ __forceinline__ float fast_tanh(float v) {
    return 1.0f - 2.0f / (__expf(2.0f * v) + 1.0f);
}

// warp tree reduction: 32 accs over 32 lanes; lane l ends with sum of acc l.
__device__ __forceinline__ void reduce32(float* acc, int lane) {
#pragma unroll
    for (int off = 16; off >= 1; off >>= 1) {
        const int half = off;
        const bool up = (lane & off) != 0;
#pragma unroll
        for (int i = 0; i < 16; i++) {
            if (i < half) {
                float send = up ? acc[i] : acc[i + half];
                float got  = __shfl_xor_sync(0xffffffffu, send, off);
                acc[i] = (up ? acc[i + half] : acc[i]) + got;
            }
        }
    }
}
// 16 accs over 32 lanes; lane pair {2o,2o+1} both end with sum of acc o=lane>>1.
__device__ __forceinline__ void reduce16dup(float* acc, int lane) {
#pragma unroll
    for (int off = 16; off >= 2; off >>= 1) {
        const int half = off >> 1;
        const bool up = (lane & off) != 0;
#pragma unroll
        for (int i = 0; i < 8; i++) {
            if (i < half) {
                float send = up ? acc[i] : acc[i + half];
                float got  = __shfl_xor_sync(0xffffffffu, send, off);
                acc[i] = (up ? acc[i + half] : acc[i]) + got;
            }
        }
    }
    acc[0] += __shfl_xor_sync(0xffffffffu, acc[0], 1);
}

// =====================================================================
// Kernel B: persistent recurrence — EXACT R6 compute structure
// (plain fp32 accs, 4b x 8r warp tiles, no k-split) with fence-free
// acq/rel group barriers and folded init/final.
// 128 CTAs x 512 threads, 1 CTA/SM. Group g (16 CTAs) owns batches
// [8g,8g+8); CTA owns hidden rows [32*cid, 32*cid+32).
// =====================================================================
__global__ void __launch_bounds__(RTHREADS, 1) gru_rec_kernel(
    float* __restrict__ out,
    const float* __restrict__ Wr,
    const float* __restrict__ Wz,
    const float* __restrict__ Wg,
    int write_final)
{
    extern __shared__ float sm[];
    float* wrz = sm;                    // [64][512] rows 0..31 Wr_h, 32..63 Wz_h
    float* wg  = wrz + 64 * 512;        // [32][512] Wg_h
    float* hs  = wg  + 32 * 512;        // [8][512]  h (phase1) / r*h (phase2)
    float* zs  = hs  + 8 * 512;         // [8][32]
    float* hps = zs  + 256;             // [8][32]

    const int cta = blockIdx.x;
    const int grp = cta >> 4;
    const int cid = cta & 15;
    const int n0 = cid * RPC;
    const int b0 = grp * BLOC;
    const int tid = threadIdx.x;
    const int w = tid >> 5, lane = tid & 31;

    // ---- load hidden-part weights into smem (once) ----
    for (int idx = tid; idx < 64 * 128; idx += RTHREADS) {
        int row = idx >> 7, c4 = idx & 127;
        const float* W = (row < 32) ? Wr : Wz;
        int n = n0 + (row & 31);
        ((float4*)wrz)[idx] = *(const float4*)&W[(size_t)n * 1024 + 512 + c4 * 4];
    }
    for (int idx = tid; idx < 32 * 128; idx += RTHREADS) {
        int row = idx >> 7, c4 = idx & 127;
        ((float4*)wg)[idx] = *(const float4*)&Wg[(size_t)(n0 + row) * 1024 + 512 + c4 * 4];
    }
    __syncthreads();

    // phase1 mapping: warp tile 4 batches x 8 rows (rows 0..63 = r|z)
    const int p1_bb  = (w & 1) * 4;
    const int p1_rb  = (w >> 1) * 8;
    const int p1_bl  = p1_bb + (lane >> 3);
    const int p1_row = p1_rb + (lane & 7);             // 0..63
    const bool p1_isR = p1_row < 32;
    const int p1_nl  = p1_row & 31;
    const int p1_n   = n0 + p1_nl;
    const int p1_b   = b0 + p1_bl;
    const int p1_col = (p1_isR ? 0 : 512) + p1_n;
    // phase2 mapping: warp tile 4 batches x 4 rows; output o2 = lane>>1
    const int p2_bb = (w & 1) * 4;
    const int p2_rb = (w >> 1) * 4;
    const int o2    = lane >> 1;
    const int p2_bl = p2_bb + (o2 >> 2);
    const int p2_nl = p2_rb + (o2 & 3);
    const int p2_b  = b0 + p2_bl;
    const int p2_n  = n0 + p2_nl;

    const float4* hs4  = (const float4*)hs;
    const float4* wrz4 = (const float4*)wrz;
    const float4* wg4  = (const float4*)wg;

    const float* xrow = g_Xbuf;
    for (int t = 0; t < T_STEPS; t++, xrow += (size_t)BATCH * XCOLS) {
        // generation snapshots (before any of our arrivals this step)
        const unsigned my1 = ld_acq(&g_gen1[grp]);
        const unsigned my2 = ld_acq(&g_gen2[grp]);

        // prefetch x pre-activations for this step (L1 persists: no fences)
        float x1v = __ldg(&xrow[(size_t)p1_b * XCOLS + p1_col]);
        float x2v = __ldg(&xrow[(size_t)p2_b * XCOLS + 1024 + p2_n]);

        // ---- stage h (zeros at t==0; L2-coherent after) ----
        if (t == 0) {
            float4 z4 = {0.f, 0.f, 0.f, 0.f};
#pragma unroll
            for (int it = 0; it < 2; it++)
                ((float4*)hs)[tid + it * RTHREADS] = z4;
        } else {
#pragma unroll
            for (int it = 0; it < 2; it++) {
                int idx = tid + it * RTHREADS;
                ((float4*)hs)[idx] = __ldcg(&((const float4*)g_h)[b0 * 128 + idx]);
            }
        }
        __syncthreads();

        // ================= phase 1: r and z =================
        {
            float acc[32];
#pragma unroll
            for (int i = 0; i < 32; i++) acc[i] = 0.0f;
#pragma unroll
            for (int j = 0; j < 4; j++) {
                const int o = lane + j * 32;
                float4 hv[4];
#pragma unroll
                for (int bbx = 0; bbx < 4; bbx++)
                    hv[bbx] = hs4[(p1_bb + bbx) * 128 + o];
#pragma unroll
                for (int rr = 0; rr < 8; rr++) {
                    float4 wv = wrz4[(p1_rb + rr) * 128 + o];
#pragma unroll
                    for (int bbx = 0; bbx < 4; bbx++)
                        acc[bbx * 8 + rr] += dot4f(hv[bbx], wv);
                }
            }
            reduce32(acc, lane);
            float sg = fast_sigmoid(x1v + acc[0]);
            if (p1_isR) {
                stg_strong(&g_rh[p1_b * 512 + p1_n], sg * hs[p1_bl * 512 + p1_n]);
            } else {
                zs[p1_bl * 32 + p1_nl]  = sg;
                hps[p1_bl * 32 + p1_nl] = hs[p1_bl * 512 + p1_n];
            }
        }
        // ---- barrier 1 (fence-free acq/rel) ----
        __syncthreads();
        if (tid == 0) {
            unsigned old = atom_add_rel(&g_cnt1[grp], 1u);
            if (old == CPG - 1u) {
                st_rlx_u32(&g_cnt1[grp], 0u);
                st_rel_u32(&g_gen1[grp], my1 + 1u);
            }
            while (ld_acq(&g_gen1[grp]) == my1) { }
        }
        __syncthreads();

        // ---- stage r*h (overwrites hs) ----
#pragma unroll
        for (int it = 0; it < 2; it++) {
            int idx = tid + it * RTHREADS;
            ((float4*)hs)[idx] = __ldcg(&((const float4*)g_rh)[b0 * 128 + idx]);
        }
        __syncthreads();

        // ================= phase 2: g and h update =================
        {
            float acc[16];
#pragma unroll
            for (int i = 0; i < 16; i++) acc[i] = 0.0f;
#pragma unroll
            for (int j = 0; j < 4; j++) {
                const int o = lane + j * 32;
                float4 hv[4];
#pragma unroll
                for (int bbx = 0; bbx < 4; bbx++)
                    hv[bbx] = hs4[(p2_bb + bbx) * 128 + o];
#pragma unroll
                for (int rr = 0; rr < 4; rr++) {
                    float4 wv = wg4[(p2_rb + rr) * 128 + o];
#pragma unroll
                    for (int bbx = 0; bbx < 4; bbx++)
                        acc[bbx * 4 + rr] += dot4f(hv[bbx], wv);
                }
            }
            reduce16dup(acc, lane);
            if ((lane & 1) == 0) {
                float gv = fast_tanh(x2v + acc[0]);
                float zv = zs[p2_bl * 32 + p2_nl];
                float hp = hps[p2_bl * 32 + p2_nl];
                float hn = zv * hp + (1.0f - zv) * gv;
                stg_strong(&g_h[p2_b * 512 + p2_n], hn);
                out[((size_t)t * BATCH + p2_b) * 512 + p2_n] = hn;
                if (write_final && t == T_STEPS - 1)
                    out[(size_t)T_STEPS * BATCH * 512 + p2_b * 512 + p2_n] = hn;
            }
        }
        // ---- barrier 2 (fence-free acq/rel) ----
        __syncthreads();
        if (tid == 0) {
            unsigned old = atom_add_rel(&g_cnt2[grp], 1u);
            if (old == CPG - 1u) {
                st_rlx_u32(&g_cnt2[grp], 0u);
                st_rel_u32(&g_gen2[grp], my2 + 1u);
            }
            if (t < T_STEPS - 1) {
                while (ld_acq(&g_gen2[grp]) == my2) { }
            }
        }
        if (t < T_STEPS - 1) __syncthreads();
    }
}

// =====================================================================
extern "C" void kernel_launch(void* const* d_in, const int* in_sizes, int n_in,
                              void* d_out, int out_size) {
    const float* x  = (const float*)d_in[0];
    const float* Wr = (const float*)d_in[1];
    const float* br = (const float*)d_in[2];
    const float* Wz = (const float*)d_in[3];
    const float* bz = (const float*)d_in[4];
    const float* Wg = (const float*)d_in[5];
    const float* bg = (const float*)d_in[6];
    float* out = (float*)d_out;

    dim3 gdim(MROWS / 128, XCOLS / 128);
    xproj_kernel<<<gdim, 256>>>(x, Wr, br, Wz, bz, Wg, bg);

    long long need = (long long)T_STEPS * BATCH * D_HID + (long long)BATCH * D_HID;
    int write_final = ((long long)out_size >= need) ? 1 : 0;

    const int smem_bytes = (64 * 512 + 32 * 512 + 8 * 512 + 256 + 256) * 4; // 215040
    cudaFuncSetAttribute(gru_rec_kernel,
                         cudaFuncAttributeMaxDynamicSharedMemorySize, smem_bytes);
    gru_rec_kernel<<<NCTAS, RTHREADS, smem_bytes>>>(out, Wr, Wz, Wg, write_final);
}

// round 14
// speedup vs baseline: 1.2374x; 1.0996x over previous
#include <cuda_runtime.h>
#include <cuda_bf16.h>
#include <math.h>
#include <stdint.h>
#include <stddef.h>

// ---------------- problem constants ----------------
#define T_STEPS 2048
#define BATCH   64
#define D_IN    512
#define D_HID   512
#define MROWS   (T_STEPS * BATCH)        // 131072
#define XCOLS   1536                     // r | z | g pre-activations from x

// ---------------- recurrent kernel topology ----------------
#define NGROUPS 8
#define CPG     16
#define NCTAS   (NGROUPS * CPG)          // 128
#define BLOC    (BATCH / NGROUPS)        // 8
#define RPC     (D_HID / CPG)            // 32
#define RTHREADS 512

// ---------------- device scratch (static; no allocation APIs) ----------------
__device__ float g_Xbuf[(size_t)MROWS * XCOLS];
__device__ float g_h[BATCH * D_HID];
__device__ float g_rh[BATCH * D_HID];
__device__ unsigned g_cnt1[NGROUPS];
__device__ unsigned g_gen1[NGROUPS];
__device__ unsigned g_cnt2[NGROUPS];
__device__ unsigned g_gen2[NGROUPS];

// bf16 hi/lo split operands for the tensor-core xproj
__device__ __nv_bfloat16 g_xhi[(size_t)MROWS * D_IN];   // 128 MB
__device__ __nv_bfloat16 g_xlo[(size_t)MROWS * D_IN];   // 128 MB
__device__ __nv_bfloat16 g_whi[XCOLS * D_IN];           // 1.5 MB (r|z|g rows)
__device__ __nv_bfloat16 g_wlo[XCOLS * D_IN];

// ---------------- acquire/release sync primitives ----------------
__device__ __forceinline__ unsigned ld_acq(const unsigned* p) {
    unsigned v;
    asm volatile("ld.acquire.gpu.u32 %0, [%1];" : "=r"(v) : "l"(p) : "memory");
    return v;
}
__device__ __forceinline__ unsigned atom_add_rel(unsigned* p, unsigned v) {
    unsigned old;
    asm volatile("atom.add.release.gpu.u32 %0, [%1], %2;"
                 : "=r"(old) : "l"(p), "r"(v) : "memory");
    return old;
}
__device__ __forceinline__ void st_rel_u32(unsigned* p, unsigned v) {
    asm volatile("st.release.gpu.u32 [%0], %1;" :: "l"(p), "r"(v) : "memory");
}
__device__ __forceinline__ void st_rlx_u32(unsigned* p, unsigned v) {
    asm volatile("st.relaxed.gpu.u32 [%0], %1;" :: "l"(p), "r"(v) : "memory");
}
__device__ __forceinline__ void stg_strong(float* p, float v) {
    asm volatile("st.relaxed.gpu.f32 [%0], %1;" :: "l"(p), "f"(v) : "memory");
}

// ---------------- mma.sync / ldmatrix / cp.async helpers (sm_80+ PTX) ------
__device__ __forceinline__ uint32_t smem_u32(const void* p) {
    uint32_t a;
    asm("{ .reg .u64 t; cvta.to.shared.u64 t, %1; cvt.u32.u64 %0, t; }"
        : "=r"(a) : "l"(p));
    return a;
}
__device__ __forceinline__ void ldm4(uint32_t* r, uint32_t addr) {
    asm volatile("ldmatrix.sync.aligned.m8n8.x4.shared.b16 {%0,%1,%2,%3}, [%4];"
                 : "=r"(r[0]), "=r"(r[1]), "=r"(r[2]), "=r"(r[3]) : "r"(addr));
}
__device__ __forceinline__ void mma16816(float* c, const uint32_t* a,
                                         const uint32_t* b) {
    asm volatile(
        "mma.sync.aligned.m16n8k16.row.col.f32.bf16.bf16.f32 "
        "{%0,%1,%2,%3}, {%4,%5,%6,%7}, {%8,%9}, {%0,%1,%2,%3};"
        : "+f"(c[0]), "+f"(c[1]), "+f"(c[2]), "+f"(c[3])
        : "r"(a[0]), "r"(a[1]), "r"(a[2]), "r"(a[3]), "r"(b[0]), "r"(b[1]));
}
__device__ __forceinline__ void cp16(uint32_t dst, const void* src) {
    asm volatile("cp.async.cg.shared.global [%0], [%1], 16;"
                 :: "r"(dst), "l"(__cvta_generic_to_global(src)) : "memory");
}
#define CP_COMMIT() asm volatile("cp.async.commit_group;" ::: "memory")
#define CP_WAIT1()  asm volatile("cp.async.wait_group 1;" ::: "memory")
#define CP_WAIT0()  asm volatile("cp.async.wait_group 0;" ::: "memory")

// =====================================================================
// split kernels: fp32 -> bf16 hi + bf16 lo
// =====================================================================
__global__ void __launch_bounds__(256) split_x_kernel(const float* __restrict__ x) {
    size_t i4 = (size_t)blockIdx.x * 256 + threadIdx.x;   // float4 index
    float4 v = ((const float4*)x)[i4];
    float vv[4] = {v.x, v.y, v.z, v.w};
    __nv_bfloat16 hi[4], lo[4];
#pragma unroll
    for (int j = 0; j < 4; j++) {
        hi[j] = __float2bfloat16(vv[j]);
        lo[j] = __float2bfloat16(vv[j] - __bfloat162float(hi[j]));
    }
    ((uint2*)g_xhi)[i4] = *(uint2*)hi;
    ((uint2*)g_xlo)[i4] = *(uint2*)lo;
}

__global__ void __launch_bounds__(256) split_w_kernel(
    const float* __restrict__ Wr, const float* __restrict__ Wz,
    const float* __restrict__ Wg)
{
    size_t i4 = (size_t)blockIdx.x * 256 + threadIdx.x;   // 4-elem groups
    size_t e = i4 * 4;
    int n = (int)(e >> 9);            // 0..1535
    int k = (int)(e & 511);
    int gate = n >> 9;
    int nr = n & 511;
    const float* W = (gate == 0) ? Wr : (gate == 1) ? Wz : Wg;
    float4 v = *(const float4*)&W[(size_t)nr * 1024 + k];
    float vv[4] = {v.x, v.y, v.z, v.w};
    __nv_bfloat16 hi[4], lo[4];
#pragma unroll
    for (int j = 0; j < 4; j++) {
        hi[j] = __float2bfloat16(vv[j]);
        lo[j] = __float2bfloat16(vv[j] - __bfloat162float(hi[j]));
    }
    ((uint2*)g_whi)[i4] = *(uint2*)hi;
    ((uint2*)g_wlo)[i4] = *(uint2*)lo;
}

// =====================================================================
// Kernel A: mma.sync bf16-split xproj.
//   C[m][n] = sum_k x[m][k] W[n][k], via Ahi*Bhi + Ahi*Blo + Alo*Bhi.
// CTA tile 128(m) x 64(n), BK=64, 8 warps (warp tile 32x32),
// XOR-swizzled smem rows, cp.async double buffer.
// grid (24, 1024): x = n-block (fast -> A-tile L2 reuse), y = m-block.
// =====================================================================
#define XA_HI 0
#define XA_LO 16384
#define XB_HI 32768
#define XB_LO 40960
#define XBUF  49152          // bytes per buffer
#define XSMEM (2 * XBUF)     // 96 KB

__global__ void __launch_bounds__(256, 2) xproj_tc_kernel(
    const float* __restrict__ br, const float* __restrict__ bz,
    const float* __restrict__ bg)
{
    extern __shared__ char smc[];
    const uint32_t smem_base = smem_u32(smc);
    const int tid = threadIdx.x;
    const int w = tid >> 5, lane = tid & 31;
    const int bn = blockIdx.x;            // 0..23
    const int bm = blockIdx.y;            // 0..1023
    const int m0 = bm << 7;
    const int n0w = bn << 6;              // row base in 1536-row W space

    const int wm = w & 3;                 // warp m position (x32)
    const int wn = w >> 2;                // warp n position (x32)

    // staging assignments (per chunk): A: 128 rows x 8 blks, B: 64 rows x 8 blks
    // thread handles ids tid + i*256; row = id>>3, blk = id&7; swizzled block.
    auto issue = [&](int chunk, int buf) {
        const uint32_t base = smem_base + buf * XBUF;
        const __nv_bfloat16* sAh = g_xhi + (size_t)m0 * 512 + chunk * 64;
        const __nv_bfloat16* sAl = g_xlo + (size_t)m0 * 512 + chunk * 64;
        const __nv_bfloat16* sBh = g_whi + (size_t)n0w * 512 + chunk * 64;
        const __nv_bfloat16* sBl = g_wlo + (size_t)n0w * 512 + chunk * 64;
#pragma unroll
        for (int i = 0; i < 4; i++) {
            int id = tid + i * 256;
            int row = id >> 3, blk = id & 7;
            uint32_t off = row * 128 + ((blk ^ (row & 7)) << 4);
            cp16(base + XA_HI + off, sAh + (size_t)row * 512 + blk * 8);
            cp16(base + XA_LO + off, sAl + (size_t)row * 512 + blk * 8);
        }
#pragma unroll
        for (int i = 0; i < 2; i++) {
            int id = tid + i * 256;
            int row = id >> 3, blk = id & 7;
            uint32_t off = row * 128 + ((blk ^ (row & 7)) << 4);
            cp16(base + XB_HI + off, sBh + (size_t)row * 512 + blk * 8);
            cp16(base + XB_LO + off, sBl + (size_t)row * 512 + blk * 8);
        }
        CP_COMMIT();
    };

    float c[2][4][4];
#pragma unroll
    for (int mt = 0; mt < 2; mt++)
#pragma unroll
        for (int nt = 0; nt < 4; nt++)
#pragma unroll
            for (int q = 0; q < 4; q++) c[mt][nt][q] = 0.0f;

    issue(0, 0);

#pragma unroll 1
    for (int chunk = 0; chunk < 8; chunk++) {
        const int buf = chunk & 1;
        if (chunk < 7) { issue(chunk + 1, buf ^ 1); CP_WAIT1(); }
        else           { CP_WAIT0(); }
        __syncthreads();

        const uint32_t base = smem_base + buf * XBUF;
#pragma unroll
        for (int ks = 0; ks < 4; ks++) {
            // A fragments (hi & lo): 16x16 tiles at rows wm*32 + mt*16
            uint32_t ahi[2][4], alo[2][4];
#pragma unroll
            for (int mt = 0; mt < 2; mt++) {
                int r  = wm * 32 + mt * 16 + (lane & 15);
                int cb = ks * 2 + (lane >> 4);
                uint32_t off = r * 128 + ((cb ^ (r & 7)) << 4);
                ldm4(ahi[mt], base + XA_HI + off);
                ldm4(alo[mt], base + XA_LO + off);
            }
            // B fragments: x4 covers two n8 tiles; pairs p=0,1 -> nt 0..3
            uint32_t bhi[4][2], blo[4][2];
#pragma unroll
            for (int p = 0; p < 2; p++) {
                int rn = wn * 32 + p * 16 + ((lane >> 4) << 3) + (lane & 7);
                int cb = ks * 2 + ((lane >> 3) & 1);
                uint32_t off = rn * 128 + ((cb ^ (rn & 7)) << 4);
                uint32_t th[4], tl[4];
                ldm4(th, base + XB_HI + off);
                ldm4(tl, base + XB_LO + off);
                bhi[p * 2 + 0][0] = th[0]; bhi[p * 2 + 0][1] = th[1];
                bhi[p * 2 + 1][0] = th[2]; bhi[p * 2 + 1][1] = th[3];
                blo[p * 2 + 0][0] = tl[0]; blo[p * 2 + 0][1] = tl[1];
                blo[p * 2 + 1][0] = tl[2]; blo[p * 2 + 1][1] = tl[3];
            }
#pragma unroll
            for (int mt = 0; mt < 2; mt++)
#pragma unroll
                for (int nt = 0; nt < 4; nt++) {
                    mma16816(c[mt][nt], ahi[mt], bhi[nt]);
                    mma16816(c[mt][nt], ahi[mt], blo[nt]);
                    mma16816(c[mt][nt], alo[mt], bhi[nt]);
                }
        }
        __syncthreads();
    }

    // ---- epilogue: add bias, write to g_Xbuf ----
    const int g = lane >> 2, tig = lane & 3;
#pragma unroll
    for (int mt = 0; mt < 2; mt++) {
        const int row0 = m0 + wm * 32 + mt * 16 + g;
#pragma unroll
        for (int nt = 0; nt < 4; nt++) {
            int ngb = n0w + wn * 32 + nt * 8;       // n-tile base (global 0..1535)
            int gate = ngb >> 9;
            const float* bias = (gate == 0) ? br : (gate == 1) ? bz : bg;
            int nc = ngb + 2 * tig;
            float b0 = __ldg(&bias[nc & 511]);
            float b1 = __ldg(&bias[(nc & 511) + 1]);
            float2 v0 = {c[mt][nt][0] + b0, c[mt][nt][1] + b1};
            float2 v1 = {c[mt][nt][2] + b0, c[mt][nt][3] + b1};
            *(float2*)&g_Xbuf[(size_t)row0 * XCOLS + nc]       = v0;
            *(float2*)&g_Xbuf[(size_t)(row0 + 8) * XCOLS + nc] = v1;
        }
    }
}

// =====================================================================
// Recurrence (R12, unchanged)
// =====================================================================
__device__ __forceinline__ float dot4f(float4 a, float4 b) {
    return a.x * b.x + a.y * b.y + a.z * b.z + a.w * b.w;
}
__device__ __forceinline__ float fast_sigmoid(float v) {
    return 1.0f / (1.0f + __expf(-v));
}
__device__ __forceinline__ float fast_tanh(float v) {
    return 1.0f - 2.0f / (__expf(2.0f * v) + 1.0f);
}
__device__ __forceinline__ void reduce32(float* acc, int lane) {
#pragma unroll
    for (int off = 16; off >= 1; off >>= 1) {
        const int half = off;
        const bool up = (lane & off) != 0;
#pragma unroll
        for (int i = 0; i < 16; i++) {
            if (i < half) {
                float send = up ? acc[i] : acc[i + half];
                float got  = __shfl_xor_sync(0xffffffffu, send, off);
                acc[i] = (up ? acc[i + half] : acc[i]) + got;
            }
        }
    }
}
__device__ __forceinline__ void reduce16dup(float* acc, int lane) {
#pragma unroll
    for (int off = 16; off >= 2; off >>= 1) {
        const int half = off >> 1;
        const bool up = (lane & off) != 0;
#pragma unroll
        for (int i = 0; i < 8; i++) {
            if (i < half) {
                float send = up ? acc[i] : acc[i + half];
                float got  = __shfl_xor_sync(0xffffffffu, send, off);
                acc[i] = (up ? acc[i + half] : acc[i]) + got;
            }
        }
    }
    acc[0] += __shfl_xor_sync(0xffffffffu, acc[0], 1);
}

__global__ void __launch_bounds__(RTHREADS, 1) gru_rec_kernel(
    float* __restrict__ out,
    const float* __restrict__ Wr,
    const float* __restrict__ Wz,
    const float* __restrict__ Wg,
    int write_final)
{
    extern __shared__ float sm[];
    float* wrz = sm;
    float* wg  = wrz + 64 * 512;
    float* hs  = wg  + 32 * 512;
    float* zs  = hs  + 8 * 512;
    float* hps = zs  + 256;

    const int cta = blockIdx.x;
    const int grp = cta >> 4;
    const int cid = cta & 15;
    const int n0 = cid * RPC;
    const int b0 = grp * BLOC;
    const int tid = threadIdx.x;
    const int w = tid >> 5, lane = tid & 31;

    for (int idx = tid; idx < 64 * 128; idx += RTHREADS) {
        int row = idx >> 7, c4 = idx & 127;
        const float* W = (row < 32) ? Wr : Wz;
        int n = n0 + (row & 31);
        ((float4*)wrz)[idx] = *(const float4*)&W[(size_t)n * 1024 + 512 + c4 * 4];
    }
    for (int idx = tid; idx < 32 * 128; idx += RTHREADS) {
        int row = idx >> 7, c4 = idx & 127;
        ((float4*)wg)[idx] = *(const float4*)&Wg[(size_t)(n0 + row) * 1024 + 512 + c4 * 4];
    }
    __syncthreads();

    const int p1_bb  = (w & 1) * 4;
    const int p1_rb  = (w >> 1) * 8;
    const int p1_bl  = p1_bb + (lane >> 3);
    const int p1_row = p1_rb + (lane & 7);
    const bool p1_isR = p1_row < 32;
    const int p1_nl  = p1_row & 31;
    const int p1_n   = n0 + p1_nl;
    const int p1_b   = b0 + p1_bl;
    const int p1_col = (p1_isR ? 0 : 512) + p1_n;
    const int p2_bb = (w & 1) * 4;
    const int p2_rb = (w >> 1) * 4;
    const int o2    = lane >> 1;
    const int p2_bl = p2_bb + (o2 >> 2);
    const int p2_nl = p2_rb + (o2 & 3);
    const int p2_b  = b0 + p2_bl;
    const int p2_n  = n0 + p2_nl;

    const float4* hs4  = (const float4*)hs;
    const float4* wrz4 = (const float4*)wrz;
    const float4* wg4  = (const float4*)wg;

    const float* xrow = g_Xbuf;
    for (int t = 0; t < T_STEPS; t++, xrow += (size_t)BATCH * XCOLS) {
        const unsigned my1 = ld_acq(&g_gen1[grp]);
        const unsigned my2 = ld_acq(&g_gen2[grp]);

        float x1v = __ldg(&xrow[(size_t)p1_b * XCOLS + p1_col]);
        float x2v = __ldg(&xrow[(size_t)p2_b * XCOLS + 1024 + p2_n]);

        if (t == 0) {
            float4 z4 = {0.f, 0.f, 0.f, 0.f};
#pragma unroll
            for (int it = 0; it < 2; it++)
                ((float4*)hs)[tid + it * RTHREADS] = z4;
        } else {
#pragma unroll
            for (int it = 0; it < 2; it++) {
                int idx = tid + it * RTHREADS;
                ((float4*)hs)[idx] = __ldcg(&((const float4*)g_h)[b0 * 128 + idx]);
            }
        }
        __syncthreads();

        {
            float acc[32];
#pragma unroll
            for (int i = 0; i < 32; i++) acc[i] = 0.0f;
#pragma unroll
            for (int j = 0; j < 4; j++) {
                const int o = lane + j * 32;
                float4 hv[4];
#pragma unroll
                for (int bbx = 0; bbx < 4; bbx++)
                    hv[bbx] = hs4[(p1_bb + bbx) * 128 + o];
#pragma unroll
                for (int rr = 0; rr < 8; rr++) {
                    float4 wv = wrz4[(p1_rb + rr) * 128 + o];
#pragma unroll
                    for (int bbx = 0; bbx < 4; bbx++)
                        acc[bbx * 8 + rr] += dot4f(hv[bbx], wv);
                }
            }
            reduce32(acc, lane);
            float sg = fast_sigmoid(x1v + acc[0]);
            if (p1_isR) {
                stg_strong(&g_rh[p1_b * 512 + p1_n], sg * hs[p1_bl * 512 + p1_n]);
            } else {
                zs[p1_bl * 32 + p1_nl]  = sg;
                hps[p1_bl * 32 + p1_nl] = hs[p1_bl * 512 + p1_n];
            }
        }
        __syncthreads();
        if (tid == 0) {
            unsigned old = atom_add_rel(&g_cnt1[grp], 1u);
            if (old == CPG - 1u) {
                st_rlx_u32(&g_cnt1[grp], 0u);
                st_rel_u32(&g_gen1[grp], my1 + 1u);
            }
            while (ld_acq(&g_gen1[grp]) == my1) { }
        }
        __syncthreads();

#pragma unroll
        for (int it = 0; it < 2; it++) {
            int idx = tid + it * RTHREADS;
            ((float4*)hs)[idx] = __ldcg(&((const float4*)g_rh)[b0 * 128 + idx]);
        }
        __syncthreads();

        {
            float acc[16];
#pragma unroll
            for (int i = 0; i < 16; i++) acc[i] = 0.0f;
#pragma unroll
            for (int j = 0; j < 4; j++) {
                const int o = lane + j * 32;
                float4 hv[4];
#pragma unroll
                for (int bbx = 0; bbx < 4; bbx++)
                    hv[bbx] = hs4[(p2_bb + bbx) * 128 + o];
#pragma unroll
                for (int rr = 0; rr < 4; rr++) {
                    float4 wv = wg4[(p2_rb + rr) * 128 + o];
#pragma unroll
                    for (int bbx = 0; bbx < 4; bbx++)
                        acc[bbx * 4 + rr] += dot4f(hv[bbx], wv);
                }
            }
            reduce16dup(acc, lane);
            if ((lane & 1) == 0) {
                float gv = fast_tanh(x2v + acc[0]);
                float zv = zs[p2_bl * 32 + p2_nl];
                float hp = hps[p2_bl * 32 + p2_nl];
                float hn = zv * hp + (1.0f - zv) * gv;
                stg_strong(&g_h[p2_b * 512 + p2_n], hn);
                out[((size_t)t * BATCH + p2_b) * 512 + p2_n] = hn;
                if (write_final && t == T_STEPS - 1)
                    out[(size_t)T_STEPS * BATCH * 512 + p2_b * 512 + p2_n] = hn;
            }
        }
        __syncthreads();
        if (tid == 0) {
            unsigned old = atom_add_rel(&g_cnt2[grp], 1u);
            if (old == CPG - 1u) {
                st_rlx_u32(&g_cnt2[grp], 0u);
                st_rel_u32(&g_gen2[grp], my2 + 1u);
            }
            if (t < T_STEPS - 1) {
                while (ld_acq(&g_gen2[grp]) == my2) { }
            }
        }
        if (t < T_STEPS - 1) __syncthreads();
    }
}

// =====================================================================
extern "C" void kernel_launch(void* const* d_in, const int* in_sizes, int n_in,
                              void* d_out, int out_size) {
    const float* x  = (const float*)d_in[0];
    const float* Wr = (const float*)d_in[1];
    const float* br = (const float*)d_in[2];
    const float* Wz = (const float*)d_in[3];
    const float* bz = (const float*)d_in[4];
    const float* Wg = (const float*)d_in[5];
    const float* bg = (const float*)d_in[6];
    float* out = (float*)d_out;

    // bf16 hi/lo splits
    split_x_kernel<<<(MROWS * D_IN) / (256 * 4), 256>>>(x);
    split_w_kernel<<<(XCOLS * D_IN) / (256 * 4), 256>>>(Wr, Wz, Wg);

    // tensor-core (mma.sync) input projection
    cudaFuncSetAttribute(xproj_tc_kernel,
                         cudaFuncAttributeMaxDynamicSharedMemorySize, XSMEM);
    dim3 gtc(24, 1024);
    xproj_tc_kernel<<<gtc, 256, XSMEM>>>(br, bz, bg);

    long long need = (long long)T_STEPS * BATCH * D_HID + (long long)BATCH * D_HID;
    int write_final = ((long long)out_size >= need) ? 1 : 0;

    const int smem_bytes = (64 * 512 + 32 * 512 + 8 * 512 + 256 + 256) * 4;
    cudaFuncSetAttribute(gru_rec_kernel,
                         cudaFuncAttributeMaxDynamicSharedMemorySize, smem_bytes);
    gru_rec_kernel<<<NCTAS, RTHREADS, smem_bytes>>>(out, Wr, Wz, Wg, write_final);
}